// round 2
// baseline (speedup 1.0000x reference)
#include <cuda_runtime.h>
#include <stdint.h>
#include <math.h>

// Problem constants
#define BB 2
#define TT 2048
#define CC 2048
#define NHH 16
#define HDD 128
#define MTOK (BB*TT)        // 4096
#define THREEC (3*CC)       // 6144

// ---------------- scratch (device globals; no cudaMalloc allowed) ----------------
__device__ float g_qkv[(size_t)MTOK * THREEC];      // [B*T, 3C]
__device__ float g_q[(size_t)BB*NHH*TT*HDD];        // [B*NH, T, HD]
__device__ float g_k[(size_t)BB*NHH*TT*HDD];
__device__ float g_v[(size_t)BB*NHH*TT*HDD];
__device__ float g_y[(size_t)MTOK * CC];            // [B*T, C] attention output

// =====================================================================
// GEMM: out[m,n] = scales[n] * sum_k A[m,k] * W[n,k]
// A fp32 [M,K] row-major, W int32 [N,K] row-major (harness widens int8->int32)
// Tile 128x128x16, 256 threads, 8x8 per thread.
// =====================================================================
__global__ __launch_bounds__(256) void gemm_af32_wi32(
    const float* __restrict__ A, const int* __restrict__ W,
    const float* __restrict__ scales, float* __restrict__ out,
    int Mdim, int Ndim, int Kdim)
{
    __shared__ float As[16][132];
    __shared__ float Bs[16][132];

    const int tid = threadIdx.x;
    const int ty = tid >> 4;     // 0..15 -> output rows
    const int tx = tid & 15;     // 0..15 -> output cols
    const int m0 = blockIdx.y * 128;
    const int n0 = blockIdx.x * 128;

    float acc[8][8];
#pragma unroll
    for (int i = 0; i < 8; i++)
#pragma unroll
        for (int j = 0; j < 8; j++) acc[i][j] = 0.0f;

    for (int kt = 0; kt < Kdim; kt += 16) {
        // --- load A tile (128 rows x 16 cols), store transposed As[k][m]
#pragma unroll
        for (int it = 0; it < 2; it++) {
            int f = it * 256 + tid;          // 0..511
            int r = f >> 2;                  // 0..127
            int kq = (f & 3) << 2;           // 0,4,8,12
            float4 av = *(const float4*)&A[(size_t)(m0 + r) * Kdim + kt + kq];
            As[kq + 0][r] = av.x;
            As[kq + 1][r] = av.y;
            As[kq + 2][r] = av.z;
            As[kq + 3][r] = av.w;
        }
        // --- load W tile (128 rows x 16 int32), convert to fp32, transposed
        {
            int r  = tid >> 1;               // 0..127
            int kh = (tid & 1) * 8;          // 0 or 8
            const int* wrow = W + (size_t)(n0 + r) * Kdim + kt + kh;
            int4 w0 = *(const int4*)wrow;
            int4 w1 = *(const int4*)(wrow + 4);
            Bs[kh + 0][r] = (float)w0.x;
            Bs[kh + 1][r] = (float)w0.y;
            Bs[kh + 2][r] = (float)w0.z;
            Bs[kh + 3][r] = (float)w0.w;
            Bs[kh + 4][r] = (float)w1.x;
            Bs[kh + 5][r] = (float)w1.y;
            Bs[kh + 6][r] = (float)w1.z;
            Bs[kh + 7][r] = (float)w1.w;
        }
        __syncthreads();

#pragma unroll
        for (int kk = 0; kk < 16; kk++) {
            float af[8], bf[8];
            *(float4*)&af[0] = *(const float4*)&As[kk][ty * 8];
            *(float4*)&af[4] = *(const float4*)&As[kk][ty * 8 + 4];
            *(float4*)&bf[0] = *(const float4*)&Bs[kk][tx * 8];
            *(float4*)&bf[4] = *(const float4*)&Bs[kk][tx * 8 + 4];
#pragma unroll
            for (int i = 0; i < 8; i++)
#pragma unroll
                for (int j = 0; j < 8; j++)
                    acc[i][j] = fmaf(af[i], bf[j], acc[i][j]);
        }
        __syncthreads();
    }

    // --- epilogue: per-output-col (weight-row) scale
    float sc[8];
#pragma unroll
    for (int j = 0; j < 8; j++) sc[j] = scales[n0 + tx * 8 + j];
#pragma unroll
    for (int i = 0; i < 8; i++) {
        size_t o = (size_t)(m0 + ty * 8 + i) * Ndim + n0 + tx * 8;
        float4 v0 = {acc[i][0] * sc[0], acc[i][1] * sc[1], acc[i][2] * sc[2], acc[i][3] * sc[3]};
        float4 v1 = {acc[i][4] * sc[4], acc[i][5] * sc[5], acc[i][6] * sc[6], acc[i][7] * sc[7]};
        *(float4*)&out[o]     = v0;
        *(float4*)&out[o + 4] = v1;
    }
}

// =====================================================================
// Split qkv [B,T,3C] into head-major q/k/v [B*NH, T, HD];
// L2-normalize q,k per (b,h,t) vector and multiply by qk_gain.
// One warp handles one 128-elem vector.
// =====================================================================
__global__ __launch_bounds__(256) void split_norm_kernel(
    const float* __restrict__ qkv, const float* __restrict__ gain_p,
    float* __restrict__ q, float* __restrict__ k, float* __restrict__ v)
{
    int gw = (blockIdx.x * blockDim.x + threadIdx.x) >> 5;   // global warp id
    int lane = threadIdx.x & 31;
    // gw in [0, 3*B*T*NH)
    int which = gw / (BB * TT * NHH);
    int rem = gw % (BB * TT * NHH);
    int b = rem / (TT * NHH);
    int rem2 = rem % (TT * NHH);
    int t = rem2 / NHH;
    int h = rem2 % NHH;

    const float* src = qkv + (size_t)(b * TT + t) * THREEC + which * CC + h * HDD + lane * 4;
    float4 x = *(const float4*)src;

    float* dstbuf = (which == 0) ? q : (which == 1) ? k : v;
    float* dst = dstbuf + ((size_t)(b * NHH + h) * TT + t) * HDD + lane * 4;

    if (which == 2) { *(float4*)dst = x; return; }

    float ss = x.x * x.x + x.y * x.y + x.z * x.z + x.w * x.w;
#pragma unroll
    for (int o = 16; o > 0; o >>= 1) ss += __shfl_xor_sync(0xffffffffu, ss, o);
    float n = sqrtf(ss);
    float s = gain_p[0] / fmaxf(n, 1e-12f);
    x.x *= s; x.y *= s; x.z *= s; x.w *= s;
    *(float4*)dst = x;
}

// =====================================================================
// Flash attention, causal, fp32. One block per (q-block of 64, b*h).
// BM=BN=64, HD=128. 256 threads.
// =====================================================================
#define QP 65     // Qs/Ks pitch (floats)
#define VP 132    // Vs pitch (floats), 16B-aligned rows
#define SP 65     // Ss pitch

__global__ __launch_bounds__(256) void flash_kernel(
    const float* __restrict__ Qg, const float* __restrict__ Kg,
    const float* __restrict__ Vg, float* __restrict__ Y)
{
    extern __shared__ float sm[];
    float* Qs = sm;                       // [128][65]
    float* Ks = sm + 128 * QP;            // [128][65]
    float* Vs = sm + 2 * 128 * QP;        // [64][132]
    float* Ss = Vs + 64 * VP;             // [64][65]
    float* m_s    = Ss + 64 * SP;         // [64]
    float* l_s    = m_s + 64;             // [64]
    float* corr_s = l_s + 64;             // [64]

    const int qb = blockIdx.x;
    const int bh = blockIdx.y;            // b*NH + h
    const int tid = threadIdx.x;
    const int ty = tid >> 4;              // 0..15 -> 4 rows each
    const int tx = tid & 15;              // 0..15 -> cols
    const int q0 = qb * 64;
    const float SM_SCALE = 0.08838834764831845f;  // 1/sqrt(128)

    const float* Qb = Qg + (size_t)bh * TT * HDD;
    const float* Kb = Kg + (size_t)bh * TT * HDD;
    const float* Vb = Vg + (size_t)bh * TT * HDD;

    // load Q tile transposed: Qs[d][r]
#pragma unroll
    for (int it = 0; it < 8; it++) {
        int f = it * 256 + tid;
        int r = f >> 5;
        int d = (f & 31) << 2;
        float4 qv = *(const float4*)&Qb[(size_t)(q0 + r) * HDD + d];
        Qs[(d + 0) * QP + r] = qv.x;
        Qs[(d + 1) * QP + r] = qv.y;
        Qs[(d + 2) * QP + r] = qv.z;
        Qs[(d + 3) * QP + r] = qv.w;
    }
    if (tid < 64) { m_s[tid] = -1e30f; l_s[tid] = 0.0f; }

    float acc[4][8];
#pragma unroll
    for (int i = 0; i < 4; i++)
#pragma unroll
        for (int j = 0; j < 8; j++) acc[i][j] = 0.0f;

    for (int jb = 0; jb <= qb; jb++) {
        __syncthreads();   // protect Ks/Vs/Ss reuse and Q-tile on first iter
        const int k0 = jb * 64;
        // load K (transposed) and V (row-major) tiles
#pragma unroll
        for (int it = 0; it < 8; it++) {
            int f = it * 256 + tid;
            int r = f >> 5;
            int d = (f & 31) << 2;
            float4 kv = *(const float4*)&Kb[(size_t)(k0 + r) * HDD + d];
            Ks[(d + 0) * QP + r] = kv.x;
            Ks[(d + 1) * QP + r] = kv.y;
            Ks[(d + 2) * QP + r] = kv.z;
            Ks[(d + 3) * QP + r] = kv.w;
            float4 vv = *(const float4*)&Vb[(size_t)(k0 + r) * HDD + d];
            *(float4*)&Vs[r * VP + d] = vv;
        }
        __syncthreads();

        // S = Q @ K^T  (each thread: 4x4 tile)
        float s[4][4];
#pragma unroll
        for (int i = 0; i < 4; i++)
#pragma unroll
            for (int j = 0; j < 4; j++) s[i][j] = 0.0f;

        const int ty4 = ty * 4, tx4 = tx * 4;
#pragma unroll 4
        for (int d = 0; d < 128; d++) {
            float a0 = Qs[d * QP + ty4 + 0];
            float a1 = Qs[d * QP + ty4 + 1];
            float a2 = Qs[d * QP + ty4 + 2];
            float a3 = Qs[d * QP + ty4 + 3];
            float b0 = Ks[d * QP + tx4 + 0];
            float b1 = Ks[d * QP + tx4 + 1];
            float b2 = Ks[d * QP + tx4 + 2];
            float b3 = Ks[d * QP + tx4 + 3];
            s[0][0] = fmaf(a0, b0, s[0][0]); s[0][1] = fmaf(a0, b1, s[0][1]);
            s[0][2] = fmaf(a0, b2, s[0][2]); s[0][3] = fmaf(a0, b3, s[0][3]);
            s[1][0] = fmaf(a1, b0, s[1][0]); s[1][1] = fmaf(a1, b1, s[1][1]);
            s[1][2] = fmaf(a1, b2, s[1][2]); s[1][3] = fmaf(a1, b3, s[1][3]);
            s[2][0] = fmaf(a2, b0, s[2][0]); s[2][1] = fmaf(a2, b1, s[2][1]);
            s[2][2] = fmaf(a2, b2, s[2][2]); s[2][3] = fmaf(a2, b3, s[2][3]);
            s[3][0] = fmaf(a3, b0, s[3][0]); s[3][1] = fmaf(a3, b1, s[3][1]);
            s[3][2] = fmaf(a3, b2, s[3][2]); s[3][3] = fmaf(a3, b3, s[3][3]);
        }
        // scale + causal mask + write S tile to smem
#pragma unroll
        for (int i = 0; i < 4; i++) {
            int qi = q0 + ty4 + i;
#pragma unroll
            for (int j = 0; j < 4; j++) {
                int kj = k0 + tx4 + j;
                float vsc = s[i][j] * SM_SCALE;
                if (kj > qi) vsc = -1e30f;
                Ss[(ty4 + i) * SP + tx4 + j] = vsc;
            }
        }
        __syncthreads();

        // online softmax: one thread per row (first 64 threads)
        if (tid < 64) {
            int r = tid;
            float mold = m_s[r];
            float mx = mold;
#pragma unroll 8
            for (int c = 0; c < 64; c++) mx = fmaxf(mx, Ss[r * SP + c]);
            float corr = __expf(mold - mx);
            float l = l_s[r] * corr;
#pragma unroll 8
            for (int c = 0; c < 64; c++) {
                float p = __expf(Ss[r * SP + c] - mx);
                Ss[r * SP + c] = p;
                l += p;
            }
            m_s[r] = mx; l_s[r] = l; corr_s[r] = corr;
        }
        __syncthreads();

        // acc = acc*corr + P @ V   (thread: rows ty4..+3, cols tx*8..+7)
        float cr[4];
#pragma unroll
        for (int i = 0; i < 4; i++) cr[i] = corr_s[ty4 + i];
#pragma unroll
        for (int i = 0; i < 4; i++)
#pragma unroll
            for (int j = 0; j < 8; j++) acc[i][j] *= cr[i];

        const int cx = tx * 8;
#pragma unroll 4
        for (int kk = 0; kk < 64; kk++) {
            float p0 = Ss[(ty4 + 0) * SP + kk];
            float p1 = Ss[(ty4 + 1) * SP + kk];
            float p2 = Ss[(ty4 + 2) * SP + kk];
            float p3 = Ss[(ty4 + 3) * SP + kk];
            float4 v0 = *(const float4*)&Vs[kk * VP + cx];
            float4 v1 = *(const float4*)&Vs[kk * VP + cx + 4];
            float vv[8] = {v0.x, v0.y, v0.z, v0.w, v1.x, v1.y, v1.z, v1.w};
#pragma unroll
            for (int j = 0; j < 8; j++) {
                acc[0][j] = fmaf(p0, vv[j], acc[0][j]);
                acc[1][j] = fmaf(p1, vv[j], acc[1][j]);
                acc[2][j] = fmaf(p2, vv[j], acc[2][j]);
                acc[3][j] = fmaf(p3, vv[j], acc[3][j]);
            }
        }
    }

    // epilogue: y[(b*T + qi)*C + h*HD + d] = acc / l
    const int b = bh / NHH, h = bh % NHH;
    const int ty4 = ty * 4;
#pragma unroll
    for (int i = 0; i < 4; i++) {
        int r = ty4 + i;
        float inv = 1.0f / l_s[r];
        size_t base = (size_t)(b * TT + q0 + r) * CC + h * HDD + tx * 8;
        float4 o0 = {acc[i][0] * inv, acc[i][1] * inv, acc[i][2] * inv, acc[i][3] * inv};
        float4 o1 = {acc[i][4] * inv, acc[i][5] * inv, acc[i][6] * inv, acc[i][7] * inv};
        *(float4*)&Y[base]     = o0;
        *(float4*)&Y[base + 4] = o1;
    }
}

// =====================================================================
// Launch
// =====================================================================
extern "C" void kernel_launch(void* const* d_in, const int* in_sizes, int n_in,
                              void* d_out, int out_size)
{
    const float* x           = (const float*)d_in[0];
    const int*   attn_w      = (const int*)d_in[1];    // int8 widened to int32 by harness
    const float* attn_scales = (const float*)d_in[2];
    const int*   proj_w      = (const int*)d_in[3];    // int8 widened to int32 by harness
    const float* proj_scales = (const float*)d_in[4];
    const float* qk_gain     = (const float*)d_in[5];
    float* out = (float*)d_out;

    float *p_qkv, *p_q, *p_k, *p_v, *p_y;
    cudaGetSymbolAddress((void**)&p_qkv, g_qkv);
    cudaGetSymbolAddress((void**)&p_q,   g_q);
    cudaGetSymbolAddress((void**)&p_k,   g_k);
    cudaGetSymbolAddress((void**)&p_v,   g_v);
    cudaGetSymbolAddress((void**)&p_y,   g_y);

    // 1) QKV = x @ Wa^T  (M=4096, N=6144, K=2048)
    gemm_af32_wi32<<<dim3(THREEC / 128, MTOK / 128), 256>>>(
        x, attn_w, attn_scales, p_qkv, MTOK, THREEC, CC);

    // 2) split + L2-normalize q,k (one warp per 128-vector)
    {
        int total_warps = 3 * BB * TT * NHH;       // 196608
        int blocks = total_warps / 8;              // 256 thr = 8 warps
        split_norm_kernel<<<blocks, 256>>>(p_qkv, qk_gain, p_q, p_k, p_v);
    }

    // 3) causal flash attention
    {
        size_t smem = (size_t)(2 * 128 * QP + 64 * VP + 64 * SP + 192) * sizeof(float);
        cudaFuncSetAttribute(flash_kernel, cudaFuncAttributeMaxDynamicSharedMemorySize, (int)smem);
        flash_kernel<<<dim3(TT / 64, BB * NHH), 256, smem>>>(p_q, p_k, p_v, p_y);
    }

    // 4) out = y @ Wp^T  (M=4096, N=2048, K=2048)
    gemm_af32_wi32<<<dim3(CC / 128, MTOK / 128), 256>>>(
        p_y, proj_w, proj_scales, out, MTOK, CC, CC);
}

// round 4
// speedup vs baseline: 1.7795x; 1.7795x over previous
#include <cuda_runtime.h>
#include <cuda_bf16.h>
#include <stdint.h>
#include <math.h>

// Problem constants
#define BB 2
#define TT 2048
#define CC 2048
#define NHH 16
#define HDD 128
#define MTOK (BB*TT)        // 4096
#define THREEC (3*CC)       // 6144

// ---------------- scratch (device globals) ----------------
__device__ float g_qkv[(size_t)MTOK * THREEC];
__device__ float g_q[(size_t)BB*NHH*TT*HDD];
__device__ float g_k[(size_t)BB*NHH*TT*HDD];
__device__ float g_v[(size_t)BB*NHH*TT*HDD];
__device__ float g_y[(size_t)MTOK * CC];
__device__ __nv_bfloat16 g_wa[(size_t)THREEC * CC];
__device__ __nv_bfloat16 g_wp[(size_t)CC * CC];
__device__ __nv_bfloat16 g_xhi[(size_t)MTOK * CC];
__device__ __nv_bfloat16 g_xlo[(size_t)MTOK * CC];
__device__ __nv_bfloat16 g_yhi[(size_t)MTOK * CC];
__device__ __nv_bfloat16 g_ylo[(size_t)MTOK * CC];

// ===================== helpers =====================
__device__ __forceinline__ uint32_t smem_u32(const void* p) {
    uint32_t a;
    asm("{ .reg .u64 t; cvta.to.shared.u64 t, %1; cvt.u32.u64 %0, t; }" : "=r"(a) : "l"(p));
    return a;
}
#define CP_ASYNC16(s, g) asm volatile("cp.async.cg.shared.global [%0], [%1], 16;" :: "r"(s), "l"(g))
#define CP_COMMIT()      asm volatile("cp.async.commit_group;" ::: "memory")
#define CP_WAIT(n)       asm volatile("cp.async.wait_group %0;" :: "n"(n) : "memory")

__device__ __forceinline__ void ldm_x4(uint32_t& r0, uint32_t& r1, uint32_t& r2, uint32_t& r3,
                                       uint32_t addr) {
    asm volatile("ldmatrix.sync.aligned.m8n8.x4.shared.b16 {%0,%1,%2,%3}, [%4];"
                 : "=r"(r0), "=r"(r1), "=r"(r2), "=r"(r3) : "r"(addr));
}
__device__ __forceinline__ void mma_bf16(float* c, const uint32_t* a, uint32_t b0, uint32_t b1) {
    asm volatile(
        "mma.sync.aligned.m16n8k16.row.col.f32.bf16.bf16.f32 "
        "{%0,%1,%2,%3}, {%4,%5,%6,%7}, {%8,%9}, {%0,%1,%2,%3};"
        : "+f"(c[0]), "+f"(c[1]), "+f"(c[2]), "+f"(c[3])
        : "r"(a[0]), "r"(a[1]), "r"(a[2]), "r"(a[3]), "r"(b0), "r"(b1));
}

// ===================== bf16 HMMA GEMM =====================
// out[m,n] = scales[n] * sum_k (Ahi + Alo)[m,k] * Wb[n,k]
// 128x128x32 tile, 8 warps (2x4), 3-stage cp.async pipeline.
#define BM 128
#define BN 128
#define BKK 32
#define GPAD 8
#define PKH (BKK + GPAD)           // 40 halves pitch (80 B)
#define STG_H (BM * PKH)           // halves per stage per matrix (5120)
#define NSTG 3
#define GEMM_SMEM (NSTG * STG_H * 2 * 2)   // 61440 bytes

__global__ __launch_bounds__(256) void gemm_mma_bf16(
    const __nv_bfloat16* __restrict__ Ahi, const __nv_bfloat16* __restrict__ Alo,
    const __nv_bfloat16* __restrict__ Wb,  const float* __restrict__ scales,
    float* __restrict__ out, int Ndim, int Kdim)
{
    extern __shared__ __nv_bfloat16 smg[];
    __nv_bfloat16* As = smg;
    __nv_bfloat16* Bs = smg + NSTG * STG_H;
    const uint32_t sbA = smem_u32(As);
    const uint32_t sbB = smem_u32(Bs);

    const int tid = threadIdx.x, lane = tid & 31, wid = tid >> 5;
    const int wm = (wid >> 2) * 64;     // warp m offset within tile
    const int wn = (wid & 3) * 32;      // warp n offset within tile
    const int m0 = blockIdx.y * BM;
    const int n0 = blockIdx.x * BN;
    const int KHALF = Kdim / BKK;       // chunks per pass
    const int KC = 2 * KHALF;           // virtual chunks (hi then lo)

    float c[4][4][4];
#pragma unroll
    for (int i = 0; i < 4; i++)
#pragma unroll
        for (int j = 0; j < 4; j++)
#pragma unroll
            for (int q = 0; q < 4; q++) c[i][j][q] = 0.0f;

    // per-thread load coords: 2 rows of A and 2 of B, 16B each
    const int lr = tid >> 2;            // 0..63
    const int lq = (tid & 3) * 8;       // halves 0,8,16,24

    auto load_stage = [&](int kc, int s) {
        const __nv_bfloat16* Ap = (kc < KHALF) ? Ahi : Alo;
        const int k0 = (kc % KHALF) * BKK;
#pragma unroll
        for (int half = 0; half < 2; half++) {
            int r = lr + half * 64;
            const __nv_bfloat16* ga = Ap + (size_t)(m0 + r) * Kdim + k0 + lq;
            uint32_t sa = sbA + (uint32_t)(s * STG_H + r * PKH + lq) * 2;
            CP_ASYNC16(sa, ga);
            const __nv_bfloat16* gb = Wb + (size_t)(n0 + r) * Kdim + k0 + lq;
            uint32_t sb = sbB + (uint32_t)(s * STG_H + r * PKH + lq) * 2;
            CP_ASYNC16(sb, gb);
        }
    };

    // prologue
#pragma unroll
    for (int s = 0; s < NSTG - 1; s++) { load_stage(s, s); CP_COMMIT(); }

    for (int kc = 0; kc < KC; kc++) {
        const int s = kc % NSTG;
        CP_WAIT(NSTG - 2);
        __syncthreads();
        const int kl = kc + NSTG - 1;
        if (kl < KC) load_stage(kl, kl % NSTG);
        CP_COMMIT();

        // compute on stage s: 2 k16 steps
#pragma unroll
        for (int ks = 0; ks < 2; ks++) {
            uint32_t a[4][4];
#pragma unroll
            for (int mi = 0; mi < 4; mi++) {
                int row = wm + mi * 16 + (lane & 15);
                int col = ks * 16 + (lane >> 4) * 8;
                ldm_x4(a[mi][0], a[mi][1], a[mi][2], a[mi][3],
                       sbA + (uint32_t)(s * STG_H + row * PKH + col) * 2);
            }
            uint32_t b[4][2];
#pragma unroll
            for (int ni = 0; ni < 2; ni++) {
                int row = wn + ni * 16 + (lane & 7) + ((lane >> 4) << 3);
                int col = ks * 16 + ((lane >> 3) & 1) * 8;
                uint32_t r0, r1, r2, r3;
                ldm_x4(r0, r1, r2, r3,
                       sbB + (uint32_t)(s * STG_H + row * PKH + col) * 2);
                b[ni * 2 + 0][0] = r0; b[ni * 2 + 0][1] = r1;
                b[ni * 2 + 1][0] = r2; b[ni * 2 + 1][1] = r3;
            }
#pragma unroll
            for (int mi = 0; mi < 4; mi++)
#pragma unroll
                for (int nj = 0; nj < 4; nj++)
                    mma_bf16(c[mi][nj], a[mi], b[nj][0], b[nj][1]);
        }
    }

    // epilogue: scale by per-n scales, store fp32
    const int gr = lane >> 2;           // group row 0..7
    const int gc = (lane & 3) * 2;      // col pair base
#pragma unroll
    for (int mi = 0; mi < 4; mi++) {
#pragma unroll
        for (int nj = 0; nj < 4; nj++) {
            int m = m0 + wm + mi * 16 + gr;
            int n = n0 + wn + nj * 8 + gc;
            float s0 = __ldg(&scales[n]);
            float s1 = __ldg(&scales[n + 1]);
            float2 v0 = {c[mi][nj][0] * s0, c[mi][nj][1] * s1};
            float2 v1 = {c[mi][nj][2] * s0, c[mi][nj][3] * s1};
            *(float2*)&out[(size_t)m * Ndim + n] = v0;
            *(float2*)&out[(size_t)(m + 8) * Ndim + n] = v1;
        }
    }
}

// ===================== conversions =====================
__global__ __launch_bounds__(256) void conv_w_kernel(const int* __restrict__ W,
                                                     __nv_bfloat16* __restrict__ O, int n4)
{
    int i = blockIdx.x * blockDim.x + threadIdx.x;
    if (i >= n4) return;
    int4 w = ((const int4*)W)[i];
    __nv_bfloat16 o[4] = { __int2bfloat16_rn(w.x), __int2bfloat16_rn(w.y),
                           __int2bfloat16_rn(w.z), __int2bfloat16_rn(w.w) };
    ((uint2*)O)[i] = *(uint2*)o;
}

__global__ __launch_bounds__(256) void conv_split_kernel(const float* __restrict__ X,
    __nv_bfloat16* __restrict__ HI, __nv_bfloat16* __restrict__ LO, int n4)
{
    int i = blockIdx.x * blockDim.x + threadIdx.x;
    if (i >= n4) return;
    float4 v = ((const float4*)X)[i];
    __nv_bfloat16 h[4] = { __float2bfloat16_rn(v.x), __float2bfloat16_rn(v.y),
                           __float2bfloat16_rn(v.z), __float2bfloat16_rn(v.w) };
    __nv_bfloat16 l[4] = { __float2bfloat16_rn(v.x - __bfloat162float(h[0])),
                           __float2bfloat16_rn(v.y - __bfloat162float(h[1])),
                           __float2bfloat16_rn(v.z - __bfloat162float(h[2])),
                           __float2bfloat16_rn(v.w - __bfloat162float(h[3])) };
    ((uint2*)HI)[i] = *(uint2*)h;
    ((uint2*)LO)[i] = *(uint2*)l;
}

// ===================== split + L2 norm =====================
__global__ __launch_bounds__(256) void split_norm_kernel(
    const float* __restrict__ qkv, const float* __restrict__ gain_p,
    float* __restrict__ q, float* __restrict__ k, float* __restrict__ v)
{
    int gw = (blockIdx.x * blockDim.x + threadIdx.x) >> 5;
    int lane = threadIdx.x & 31;
    int which = gw / (BB * TT * NHH);
    int rem = gw % (BB * TT * NHH);
    int b = rem / (TT * NHH);
    int rem2 = rem % (TT * NHH);
    int t = rem2 / NHH;
    int h = rem2 % NHH;

    const float* src = qkv + (size_t)(b * TT + t) * THREEC + which * CC + h * HDD + lane * 4;
    float4 x = *(const float4*)src;
    float* dstbuf = (which == 0) ? q : (which == 1) ? k : v;
    float* dst = dstbuf + ((size_t)(b * NHH + h) * TT + t) * HDD + lane * 4;
    if (which == 2) { *(float4*)dst = x; return; }

    float ss = x.x * x.x + x.y * x.y + x.z * x.z + x.w * x.w;
#pragma unroll
    for (int o = 16; o > 0; o >>= 1) ss += __shfl_xor_sync(0xffffffffu, ss, o);
    float n = sqrtf(ss);
    float s = gain_p[0] / fmaxf(n, 1e-12f);
    x.x *= s; x.y *= s; x.z *= s; x.w *= s;
    *(float4*)dst = x;
}

// ===================== flash attention (fp32 SIMT) =====================
#define QP 65
#define VP 132
#define SP 65

__global__ __launch_bounds__(256) void flash_kernel(
    const float* __restrict__ Qg, const float* __restrict__ Kg,
    const float* __restrict__ Vg, float* __restrict__ Y)
{
    extern __shared__ float sm[];
    float* Qs = sm;
    float* Ks = sm + 128 * QP;
    float* Vs = sm + 2 * 128 * QP;
    float* Ss = Vs + 64 * VP;
    float* m_s    = Ss + 64 * SP;
    float* l_s    = m_s + 64;
    float* corr_s = l_s + 64;

    const int qb = blockIdx.x;
    const int bh = blockIdx.y;
    const int tid = threadIdx.x;
    const int ty = tid >> 4;
    const int tx = tid & 15;
    const int q0 = qb * 64;
    const float SM_SCALE = 0.08838834764831845f;

    const float* Qb = Qg + (size_t)bh * TT * HDD;
    const float* Kb = Kg + (size_t)bh * TT * HDD;
    const float* Vb = Vg + (size_t)bh * TT * HDD;

#pragma unroll
    for (int it = 0; it < 8; it++) {
        int f = it * 256 + tid;
        int r = f >> 5;
        int d = (f & 31) << 2;
        float4 qv = *(const float4*)&Qb[(size_t)(q0 + r) * HDD + d];
        Qs[(d + 0) * QP + r] = qv.x;
        Qs[(d + 1) * QP + r] = qv.y;
        Qs[(d + 2) * QP + r] = qv.z;
        Qs[(d + 3) * QP + r] = qv.w;
    }
    if (tid < 64) { m_s[tid] = -1e30f; l_s[tid] = 0.0f; }

    float acc[4][8];
#pragma unroll
    for (int i = 0; i < 4; i++)
#pragma unroll
        for (int j = 0; j < 8; j++) acc[i][j] = 0.0f;

    for (int jb = 0; jb <= qb; jb++) {
        __syncthreads();
        const int k0 = jb * 64;
#pragma unroll
        for (int it = 0; it < 8; it++) {
            int f = it * 256 + tid;
            int r = f >> 5;
            int d = (f & 31) << 2;
            float4 kv = *(const float4*)&Kb[(size_t)(k0 + r) * HDD + d];
            Ks[(d + 0) * QP + r] = kv.x;
            Ks[(d + 1) * QP + r] = kv.y;
            Ks[(d + 2) * QP + r] = kv.z;
            Ks[(d + 3) * QP + r] = kv.w;
            float4 vv = *(const float4*)&Vb[(size_t)(k0 + r) * HDD + d];
            *(float4*)&Vs[r * VP + d] = vv;
        }
        __syncthreads();

        float s[4][4];
#pragma unroll
        for (int i = 0; i < 4; i++)
#pragma unroll
            for (int j = 0; j < 4; j++) s[i][j] = 0.0f;

        const int ty4 = ty * 4, tx4 = tx * 4;
#pragma unroll 4
        for (int d = 0; d < 128; d++) {
            float a0 = Qs[d * QP + ty4 + 0];
            float a1 = Qs[d * QP + ty4 + 1];
            float a2 = Qs[d * QP + ty4 + 2];
            float a3 = Qs[d * QP + ty4 + 3];
            float b0 = Ks[d * QP + tx4 + 0];
            float b1 = Ks[d * QP + tx4 + 1];
            float b2 = Ks[d * QP + tx4 + 2];
            float b3 = Ks[d * QP + tx4 + 3];
            s[0][0] = fmaf(a0, b0, s[0][0]); s[0][1] = fmaf(a0, b1, s[0][1]);
            s[0][2] = fmaf(a0, b2, s[0][2]); s[0][3] = fmaf(a0, b3, s[0][3]);
            s[1][0] = fmaf(a1, b0, s[1][0]); s[1][1] = fmaf(a1, b1, s[1][1]);
            s[1][2] = fmaf(a1, b2, s[1][2]); s[1][3] = fmaf(a1, b3, s[1][3]);
            s[2][0] = fmaf(a2, b0, s[2][0]); s[2][1] = fmaf(a2, b1, s[2][1]);
            s[2][2] = fmaf(a2, b2, s[2][2]); s[2][3] = fmaf(a2, b3, s[2][3]);
            s[3][0] = fmaf(a3, b0, s[3][0]); s[3][1] = fmaf(a3, b1, s[3][1]);
            s[3][2] = fmaf(a3, b2, s[3][2]); s[3][3] = fmaf(a3, b3, s[3][3]);
        }
#pragma unroll
        for (int i = 0; i < 4; i++) {
            int qi = q0 + ty4 + i;
#pragma unroll
            for (int j = 0; j < 4; j++) {
                int kj = k0 + tx4 + j;
                float vsc = s[i][j] * SM_SCALE;
                if (kj > qi) vsc = -1e30f;
                Ss[(ty4 + i) * SP + tx4 + j] = vsc;
            }
        }
        __syncthreads();

        if (tid < 64) {
            int r = tid;
            float mold = m_s[r];
            float mx = mold;
#pragma unroll 8
            for (int c2 = 0; c2 < 64; c2++) mx = fmaxf(mx, Ss[r * SP + c2]);
            float corr = __expf(mold - mx);
            float l = l_s[r] * corr;
#pragma unroll 8
            for (int c2 = 0; c2 < 64; c2++) {
                float p = __expf(Ss[r * SP + c2] - mx);
                Ss[r * SP + c2] = p;
                l += p;
            }
            m_s[r] = mx; l_s[r] = l; corr_s[r] = corr;
        }
        __syncthreads();

        float cr[4];
#pragma unroll
        for (int i = 0; i < 4; i++) cr[i] = corr_s[ty4 + i];
#pragma unroll
        for (int i = 0; i < 4; i++)
#pragma unroll
            for (int j = 0; j < 8; j++) acc[i][j] *= cr[i];

        const int cx = tx * 8;
#pragma unroll 4
        for (int kk = 0; kk < 64; kk++) {
            float p0 = Ss[(ty4 + 0) * SP + kk];
            float p1 = Ss[(ty4 + 1) * SP + kk];
            float p2 = Ss[(ty4 + 2) * SP + kk];
            float p3 = Ss[(ty4 + 3) * SP + kk];
            float4 v0 = *(const float4*)&Vs[kk * VP + cx];
            float4 v1 = *(const float4*)&Vs[kk * VP + cx + 4];
            float vv[8] = {v0.x, v0.y, v0.z, v0.w, v1.x, v1.y, v1.z, v1.w};
#pragma unroll
            for (int j = 0; j < 8; j++) {
                acc[0][j] = fmaf(p0, vv[j], acc[0][j]);
                acc[1][j] = fmaf(p1, vv[j], acc[1][j]);
                acc[2][j] = fmaf(p2, vv[j], acc[2][j]);
                acc[3][j] = fmaf(p3, vv[j], acc[3][j]);
            }
        }
    }

    const int b = bh / NHH, h = bh % NHH;
    const int ty4 = ty * 4;
#pragma unroll
    for (int i = 0; i < 4; i++) {
        int r = ty4 + i;
        float inv = 1.0f / l_s[r];
        size_t base = (size_t)(b * TT + q0 + r) * CC + h * HDD + tx * 8;
        float4 o0 = {acc[i][0] * inv, acc[i][1] * inv, acc[i][2] * inv, acc[i][3] * inv};
        float4 o1 = {acc[i][4] * inv, acc[i][5] * inv, acc[i][6] * inv, acc[i][7] * inv};
        *(float4*)&Y[base]     = o0;
        *(float4*)&Y[base + 4] = o1;
    }
}

// ===================== launch =====================
extern "C" void kernel_launch(void* const* d_in, const int* in_sizes, int n_in,
                              void* d_out, int out_size)
{
    const float* x           = (const float*)d_in[0];
    const int*   attn_w      = (const int*)d_in[1];
    const float* attn_scales = (const float*)d_in[2];
    const int*   proj_w      = (const int*)d_in[3];
    const float* proj_scales = (const float*)d_in[4];
    const float* qk_gain     = (const float*)d_in[5];
    float* out = (float*)d_out;

    float *p_qkv, *p_q, *p_k, *p_v, *p_y;
    __nv_bfloat16 *p_wa, *p_wp, *p_xhi, *p_xlo, *p_yhi, *p_ylo;
    cudaGetSymbolAddress((void**)&p_qkv, g_qkv);
    cudaGetSymbolAddress((void**)&p_q,   g_q);
    cudaGetSymbolAddress((void**)&p_k,   g_k);
    cudaGetSymbolAddress((void**)&p_v,   g_v);
    cudaGetSymbolAddress((void**)&p_y,   g_y);
    cudaGetSymbolAddress((void**)&p_wa,  g_wa);
    cudaGetSymbolAddress((void**)&p_wp,  g_wp);
    cudaGetSymbolAddress((void**)&p_xhi, g_xhi);
    cudaGetSymbolAddress((void**)&p_xlo, g_xlo);
    cudaGetSymbolAddress((void**)&p_yhi, g_yhi);
    cudaGetSymbolAddress((void**)&p_ylo, g_ylo);

    size_t fsm = (size_t)(2 * 128 * QP + 64 * VP + 64 * SP + 192) * sizeof(float);
    cudaFuncSetAttribute(gemm_mma_bf16, cudaFuncAttributeMaxDynamicSharedMemorySize, GEMM_SMEM);
    cudaFuncSetAttribute(flash_kernel, cudaFuncAttributeMaxDynamicSharedMemorySize, (int)fsm);

    // 0) weight conversions (int32 -> bf16, exact)
    conv_w_kernel<<<(THREEC * CC / 4 + 255) / 256, 256>>>(attn_w, p_wa, THREEC * CC / 4);
    conv_w_kernel<<<(CC * CC / 4 + 255) / 256, 256>>>(proj_w, p_wp, CC * CC / 4);

    // 1) x -> hi/lo bf16
    conv_split_kernel<<<(MTOK * CC / 4 + 255) / 256, 256>>>(x, p_xhi, p_xlo, MTOK * CC / 4);

    // 2) QKV = x @ Wa^T  (HMMA tensor cores)
    gemm_mma_bf16<<<dim3(THREEC / BN, MTOK / BM), 256, GEMM_SMEM>>>(
        p_xhi, p_xlo, p_wa, attn_scales, p_qkv, THREEC, CC);

    // 3) split + L2 norm
    split_norm_kernel<<<3 * BB * TT * NHH / 8, 256>>>(p_qkv, qk_gain, p_q, p_k, p_v);

    // 4) causal flash attention (fp32)
    flash_kernel<<<dim3(TT / 64, BB * NHH), 256, fsm>>>(p_q, p_k, p_v, p_y);

    // 5) y -> hi/lo bf16
    conv_split_kernel<<<(MTOK * CC / 4 + 255) / 256, 256>>>(p_y, p_yhi, p_ylo, MTOK * CC / 4);

    // 6) out = y @ Wp^T  (HMMA tensor cores)
    gemm_mma_bf16<<<dim3(CC / BN, MTOK / BM), 256, GEMM_SMEM>>>(
        p_yhi, p_ylo, p_wp, proj_scales, out, CC, CC);
}

// round 5
// speedup vs baseline: 2.7082x; 1.5219x over previous
#include <cuda_runtime.h>
#include <cuda_bf16.h>
#include <stdint.h>
#include <math.h>

// Problem constants
#define BB 2
#define TT 2048
#define CC 2048
#define NHH 16
#define HDD 128
#define MTOK (BB*TT)        // 4096
#define THREEC (3*CC)       // 6144

// ---------------- scratch (device globals) ----------------
__device__ float g_qkv[(size_t)MTOK * THREEC];
__device__ __nv_bfloat16 g_wa[(size_t)THREEC * CC];
__device__ __nv_bfloat16 g_wp[(size_t)CC * CC];
__device__ __nv_bfloat16 g_xhi[(size_t)MTOK * CC];
__device__ __nv_bfloat16 g_xlo[(size_t)MTOK * CC];
__device__ __nv_bfloat16 g_qhi[(size_t)BB*NHH*TT*HDD];
__device__ __nv_bfloat16 g_qlo[(size_t)BB*NHH*TT*HDD];
__device__ __nv_bfloat16 g_khi[(size_t)BB*NHH*TT*HDD];
__device__ __nv_bfloat16 g_klo[(size_t)BB*NHH*TT*HDD];
__device__ __nv_bfloat16 g_vhi[(size_t)BB*NHH*TT*HDD];
__device__ __nv_bfloat16 g_vlo[(size_t)BB*NHH*TT*HDD];
__device__ __nv_bfloat16 g_yhi[(size_t)MTOK * CC];
__device__ __nv_bfloat16 g_ylo[(size_t)MTOK * CC];

// ===================== helpers =====================
__device__ __forceinline__ uint32_t smem_u32(const void* p) {
    uint32_t a;
    asm("{ .reg .u64 t; cvta.to.shared.u64 t, %1; cvt.u32.u64 %0, t; }" : "=r"(a) : "l"(p));
    return a;
}
#define CP_ASYNC16(s, g) asm volatile("cp.async.cg.shared.global [%0], [%1], 16;" :: "r"(s), "l"(g))
#define CP_COMMIT()      asm volatile("cp.async.commit_group;" ::: "memory")
#define CP_WAIT(n)       asm volatile("cp.async.wait_group %0;" :: "n"(n) : "memory")

__device__ __forceinline__ void ldm_x4(uint32_t& r0, uint32_t& r1, uint32_t& r2, uint32_t& r3,
                                       uint32_t addr) {
    asm volatile("ldmatrix.sync.aligned.m8n8.x4.shared.b16 {%0,%1,%2,%3}, [%4];"
                 : "=r"(r0), "=r"(r1), "=r"(r2), "=r"(r3) : "r"(addr));
}
__device__ __forceinline__ void ldm_x4_t(uint32_t& r0, uint32_t& r1, uint32_t& r2, uint32_t& r3,
                                         uint32_t addr) {
    asm volatile("ldmatrix.sync.aligned.m8n8.x4.trans.shared.b16 {%0,%1,%2,%3}, [%4];"
                 : "=r"(r0), "=r"(r1), "=r"(r2), "=r"(r3) : "r"(addr));
}
__device__ __forceinline__ void mma_bf16(float* c, const uint32_t* a, uint32_t b0, uint32_t b1) {
    asm volatile(
        "mma.sync.aligned.m16n8k16.row.col.f32.bf16.bf16.f32 "
        "{%0,%1,%2,%3}, {%4,%5,%6,%7}, {%8,%9}, {%0,%1,%2,%3};"
        : "+f"(c[0]), "+f"(c[1]), "+f"(c[2]), "+f"(c[3])
        : "r"(a[0]), "r"(a[1]), "r"(a[2]), "r"(a[3]), "r"(b0), "r"(b1));
}

// ===================== bf16 HMMA weight GEMM =====================
#define BM 128
#define BN 128
#define BKK 32
#define GPAD 8
#define PKH (BKK + GPAD)
#define STG_H (BM * PKH)
#define NSTG 3
#define GEMM_SMEM (NSTG * STG_H * 2 * 2)

__global__ __launch_bounds__(256) void gemm_mma_bf16(
    const __nv_bfloat16* __restrict__ Ahi, const __nv_bfloat16* __restrict__ Alo,
    const __nv_bfloat16* __restrict__ Wb,  const float* __restrict__ scales,
    float* __restrict__ out, int Ndim, int Kdim)
{
    extern __shared__ __nv_bfloat16 smg[];
    __nv_bfloat16* As = smg;
    __nv_bfloat16* Bs = smg + NSTG * STG_H;
    const uint32_t sbA = smem_u32(As);
    const uint32_t sbB = smem_u32(Bs);

    const int tid = threadIdx.x, lane = tid & 31, wid = tid >> 5;
    const int wm = (wid >> 2) * 64;
    const int wn = (wid & 3) * 32;
    const int m0 = blockIdx.y * BM;
    const int n0 = blockIdx.x * BN;
    const int KHALF = Kdim / BKK;
    const int KC = 2 * KHALF;

    float c[4][4][4];
#pragma unroll
    for (int i = 0; i < 4; i++)
#pragma unroll
        for (int j = 0; j < 4; j++)
#pragma unroll
            for (int q = 0; q < 4; q++) c[i][j][q] = 0.0f;

    const int lr = tid >> 2;
    const int lq = (tid & 3) * 8;

    auto load_stage = [&](int kc, int s) {
        const __nv_bfloat16* Ap = (kc < KHALF) ? Ahi : Alo;
        const int k0 = (kc % KHALF) * BKK;
#pragma unroll
        for (int half = 0; half < 2; half++) {
            int r = lr + half * 64;
            const __nv_bfloat16* ga = Ap + (size_t)(m0 + r) * Kdim + k0 + lq;
            uint32_t sa = sbA + (uint32_t)(s * STG_H + r * PKH + lq) * 2;
            CP_ASYNC16(sa, ga);
            const __nv_bfloat16* gb = Wb + (size_t)(n0 + r) * Kdim + k0 + lq;
            uint32_t sb = sbB + (uint32_t)(s * STG_H + r * PKH + lq) * 2;
            CP_ASYNC16(sb, gb);
        }
    };

#pragma unroll
    for (int s = 0; s < NSTG - 1; s++) { load_stage(s, s); CP_COMMIT(); }

    for (int kc = 0; kc < KC; kc++) {
        const int s = kc % NSTG;
        CP_WAIT(NSTG - 2);
        __syncthreads();
        const int kl = kc + NSTG - 1;
        if (kl < KC) load_stage(kl, kl % NSTG);
        CP_COMMIT();

#pragma unroll
        for (int ks = 0; ks < 2; ks++) {
            uint32_t a[4][4];
#pragma unroll
            for (int mi = 0; mi < 4; mi++) {
                int row = wm + mi * 16 + (lane & 15);
                int col = ks * 16 + (lane >> 4) * 8;
                ldm_x4(a[mi][0], a[mi][1], a[mi][2], a[mi][3],
                       sbA + (uint32_t)(s * STG_H + row * PKH + col) * 2);
            }
            uint32_t b[4][2];
#pragma unroll
            for (int ni = 0; ni < 2; ni++) {
                int row = wn + ni * 16 + (lane & 7) + ((lane >> 4) << 3);
                int col = ks * 16 + ((lane >> 3) & 1) * 8;
                uint32_t r0, r1, r2, r3;
                ldm_x4(r0, r1, r2, r3,
                       sbB + (uint32_t)(s * STG_H + row * PKH + col) * 2);
                b[ni * 2 + 0][0] = r0; b[ni * 2 + 0][1] = r1;
                b[ni * 2 + 1][0] = r2; b[ni * 2 + 1][1] = r3;
            }
#pragma unroll
            for (int mi = 0; mi < 4; mi++)
#pragma unroll
                for (int nj = 0; nj < 4; nj++)
                    mma_bf16(c[mi][nj], a[mi], b[nj][0], b[nj][1]);
        }
    }

    const int gr = lane >> 2;
    const int gc = (lane & 3) * 2;
#pragma unroll
    for (int mi = 0; mi < 4; mi++) {
#pragma unroll
        for (int nj = 0; nj < 4; nj++) {
            int m = m0 + wm + mi * 16 + gr;
            int n = n0 + wn + nj * 8 + gc;
            float s0 = __ldg(&scales[n]);
            float s1 = __ldg(&scales[n + 1]);
            float2 v0 = {c[mi][nj][0] * s0, c[mi][nj][1] * s1};
            float2 v1 = {c[mi][nj][2] * s0, c[mi][nj][3] * s1};
            *(float2*)&out[(size_t)m * Ndim + n] = v0;
            *(float2*)&out[(size_t)(m + 8) * Ndim + n] = v1;
        }
    }
}

// ===================== conversions =====================
__global__ __launch_bounds__(256) void conv_w_kernel(const int* __restrict__ W,
                                                     __nv_bfloat16* __restrict__ O, int n4)
{
    int i = blockIdx.x * blockDim.x + threadIdx.x;
    if (i >= n4) return;
    int4 w = ((const int4*)W)[i];
    __nv_bfloat16 o[4] = { __int2bfloat16_rn(w.x), __int2bfloat16_rn(w.y),
                           __int2bfloat16_rn(w.z), __int2bfloat16_rn(w.w) };
    ((uint2*)O)[i] = *(uint2*)o;
}

__global__ __launch_bounds__(256) void conv_split_kernel(const float* __restrict__ X,
    __nv_bfloat16* __restrict__ HI, __nv_bfloat16* __restrict__ LO, int n4)
{
    int i = blockIdx.x * blockDim.x + threadIdx.x;
    if (i >= n4) return;
    float4 v = ((const float4*)X)[i];
    __nv_bfloat16 h[4] = { __float2bfloat16_rn(v.x), __float2bfloat16_rn(v.y),
                           __float2bfloat16_rn(v.z), __float2bfloat16_rn(v.w) };
    __nv_bfloat16 l[4] = { __float2bfloat16_rn(v.x - __bfloat162float(h[0])),
                           __float2bfloat16_rn(v.y - __bfloat162float(h[1])),
                           __float2bfloat16_rn(v.z - __bfloat162float(h[2])),
                           __float2bfloat16_rn(v.w - __bfloat162float(h[3])) };
    ((uint2*)HI)[i] = *(uint2*)h;
    ((uint2*)LO)[i] = *(uint2*)l;
}

// ===================== split + L2 norm -> bf16 hi/lo =====================
__global__ __launch_bounds__(256) void split_norm_kernel(
    const float* __restrict__ qkv, const float* __restrict__ gain_p,
    __nv_bfloat16* __restrict__ qhi, __nv_bfloat16* __restrict__ qlo,
    __nv_bfloat16* __restrict__ khi, __nv_bfloat16* __restrict__ klo,
    __nv_bfloat16* __restrict__ vhi, __nv_bfloat16* __restrict__ vlo)
{
    int gw = (blockIdx.x * blockDim.x + threadIdx.x) >> 5;
    int lane = threadIdx.x & 31;
    int which = gw / (BB * TT * NHH);
    int rem = gw % (BB * TT * NHH);
    int b = rem / (TT * NHH);
    int rem2 = rem % (TT * NHH);
    int t = rem2 / NHH;
    int h = rem2 % NHH;

    const float* src = qkv + (size_t)(b * TT + t) * THREEC + which * CC + h * HDD + lane * 4;
    float4 x = *(const float4*)src;

    if (which != 2) {
        float ss = x.x * x.x + x.y * x.y + x.z * x.z + x.w * x.w;
#pragma unroll
        for (int o = 16; o > 0; o >>= 1) ss += __shfl_xor_sync(0xffffffffu, ss, o);
        float n = sqrtf(ss);
        float s = gain_p[0] / fmaxf(n, 1e-12f);
        x.x *= s; x.y *= s; x.z *= s; x.w *= s;
    }

    __nv_bfloat16* HI = (which == 0) ? qhi : (which == 1) ? khi : vhi;
    __nv_bfloat16* LO = (which == 0) ? qlo : (which == 1) ? klo : vlo;
    size_t base = ((size_t)(b * NHH + h) * TT + t) * HDD + lane * 4;

    float xv[4] = {x.x, x.y, x.z, x.w};
    __nv_bfloat16 hh[4], ll[4];
#pragma unroll
    for (int i = 0; i < 4; i++) {
        hh[i] = __float2bfloat16_rn(xv[i]);
        ll[i] = __float2bfloat16_rn(xv[i] - __bfloat162float(hh[i]));
    }
    *(uint2*)&HI[base] = *(uint2*)hh;
    *(uint2*)&LO[base] = *(uint2*)ll;
}

// ===================== HMMA flash attention =====================
// Block: 64 q-rows, 128 threads (4 warps, 16 rows each). BN=64 keys/iter.
// S = Qhi·Khi + Qhi·Klo + Qlo·Khi (fp32 accum); P hi/lo; O += Phi·Vhi + Phi·Vlo + Plo·Vhi.
#define FPH 136   // smem pitch in halves
#define FQHI 0
#define FQLO (64*FPH)
#define FKHI (2*64*FPH)
#define FKLO (3*64*FPH)
#define FVHI (4*64*FPH)
#define FVLO (5*64*FPH)
#define FLASH_SMEM (6*64*FPH*2)    // 104448 bytes

__global__ __launch_bounds__(128) void flash_mma_kernel(
    const __nv_bfloat16* __restrict__ Qhi, const __nv_bfloat16* __restrict__ Qlo,
    const __nv_bfloat16* __restrict__ Khi, const __nv_bfloat16* __restrict__ Klo,
    const __nv_bfloat16* __restrict__ Vhi, const __nv_bfloat16* __restrict__ Vlo,
    __nv_bfloat16* __restrict__ Yhi, __nv_bfloat16* __restrict__ Ylo)
{
    extern __shared__ __nv_bfloat16 fsm[];
    const uint32_t sb = smem_u32(fsm);
    const int tid = threadIdx.x, lane = tid & 31, wid = tid >> 5;
    const int wr = wid * 16;                 // warp's first q-row in tile
    const int qb = blockIdx.x, bh = blockIdx.y;
    const int q0 = qb * 64;
    const float SCALE = 0.08838834764831845f;   // 1/sqrt(128)

    const size_t bhoff = (size_t)bh * TT * HDD;
    const __nv_bfloat16* Qh = Qhi + bhoff;
    const __nv_bfloat16* Ql = Qlo + bhoff;
    const __nv_bfloat16* Kh = Khi + bhoff;
    const __nv_bfloat16* Kl = Klo + bhoff;
    const __nv_bfloat16* Vh = Vhi + bhoff;
    const __nv_bfloat16* Vl = Vlo + bhoff;

    // ---- load Q tiles (64x128) hi/lo into smem
    {
        const int row = tid >> 1;                 // 0..63
        const int c = (tid & 1) * 64;             // halves 0 or 64
#pragma unroll
        for (int q8 = 0; q8 < 64; q8 += 8) {
            uint4 vh_ = *(const uint4*)(Qh + (size_t)(q0 + row) * HDD + c + q8);
            uint4 vl_ = *(const uint4*)(Ql + (size_t)(q0 + row) * HDD + c + q8);
            uint32_t so = (row * FPH + c + q8) * 2;
            *(uint2*)((char*)fsm + FQHI * 2 + so)     = make_uint2(vh_.x, vh_.y);
            *(uint2*)((char*)fsm + FQHI * 2 + so + 8) = make_uint2(vh_.z, vh_.w);
            *(uint2*)((char*)fsm + FQLO * 2 + so)     = make_uint2(vl_.x, vl_.y);
            *(uint2*)((char*)fsm + FQLO * 2 + so + 8) = make_uint2(vl_.z, vl_.w);
        }
    }

    float o[16][4];
#pragma unroll
    for (int i = 0; i < 16; i++)
#pragma unroll
        for (int j = 0; j < 4; j++) o[i][j] = 0.0f;
    float m0v = -1e30f, m1v = -1e30f, l0 = 0.0f, l1 = 0.0f;

    for (int jb = 0; jb <= qb; jb++) {
        const int k0 = jb * 64;
        __syncthreads();
        // ---- load K/V hi/lo tiles (64x128 each)
        {
            const int row = tid >> 1;
            const int c = (tid & 1) * 64;
#pragma unroll
            for (int q8 = 0; q8 < 64; q8 += 8) {
                uint32_t so = (row * FPH + c + q8) * 2;
                uint4 a0 = *(const uint4*)(Kh + (size_t)(k0 + row) * HDD + c + q8);
                *(uint2*)((char*)fsm + FKHI * 2 + so)     = make_uint2(a0.x, a0.y);
                *(uint2*)((char*)fsm + FKHI * 2 + so + 8) = make_uint2(a0.z, a0.w);
                uint4 a1 = *(const uint4*)(Kl + (size_t)(k0 + row) * HDD + c + q8);
                *(uint2*)((char*)fsm + FKLO * 2 + so)     = make_uint2(a1.x, a1.y);
                *(uint2*)((char*)fsm + FKLO * 2 + so + 8) = make_uint2(a1.z, a1.w);
                uint4 a2 = *(const uint4*)(Vh + (size_t)(k0 + row) * HDD + c + q8);
                *(uint2*)((char*)fsm + FVHI * 2 + so)     = make_uint2(a2.x, a2.y);
                *(uint2*)((char*)fsm + FVHI * 2 + so + 8) = make_uint2(a2.z, a2.w);
                uint4 a3 = *(const uint4*)(Vl + (size_t)(k0 + row) * HDD + c + q8);
                *(uint2*)((char*)fsm + FVLO * 2 + so)     = make_uint2(a3.x, a3.y);
                *(uint2*)((char*)fsm + FVLO * 2 + so + 8) = make_uint2(a3.z, a3.w);
            }
        }
        __syncthreads();

        // ---- S = QK^T 3-pass
        float s[8][4];
#pragma unroll
        for (int i = 0; i < 8; i++)
#pragma unroll
            for (int j = 0; j < 4; j++) s[i][j] = 0.0f;

#pragma unroll
        for (int ks = 0; ks < 8; ks++) {
            uint32_t ah[4], al[4];
            uint32_t qoff = sb + (uint32_t)((wr + (lane & 15)) * FPH + ks * 16 + (lane >> 4) * 8) * 2;
            ldm_x4(ah[0], ah[1], ah[2], ah[3], qoff + FQHI * 2);
            ldm_x4(al[0], al[1], al[2], al[3], qoff + FQLO * 2);
#pragma unroll
            for (int nt2 = 0; nt2 < 4; nt2++) {
                uint32_t koff = sb + (uint32_t)((nt2 * 16 + (lane & 7) + ((lane >> 4) << 3)) * FPH
                                                + ks * 16 + ((lane >> 3) & 1) * 8) * 2;
                uint32_t bh0, bh1, bh2, bh3, bl0, bl1, bl2, bl3;
                ldm_x4(bh0, bh1, bh2, bh3, koff + FKHI * 2);
                ldm_x4(bl0, bl1, bl2, bl3, koff + FKLO * 2);
                mma_bf16(s[nt2 * 2 + 0], ah, bh0, bh1);
                mma_bf16(s[nt2 * 2 + 1], ah, bh2, bh3);
                mma_bf16(s[nt2 * 2 + 0], ah, bl0, bl1);
                mma_bf16(s[nt2 * 2 + 1], ah, bl2, bl3);
                mma_bf16(s[nt2 * 2 + 0], al, bh0, bh1);
                mma_bf16(s[nt2 * 2 + 1], al, bh2, bh3);
            }
        }

        // ---- scale + causal mask
        const int lr0 = wr + (lane >> 2);      // local row of c0/c1 (within 64)
        const int lc0 = (lane & 3) * 2;
#pragma unroll
        for (int nt = 0; nt < 8; nt++) {
#pragma unroll
            for (int j = 0; j < 4; j++) s[nt][j] *= SCALE;
            if (jb == qb) {
                int col = nt * 8 + lc0;
                if (col > lr0)     s[nt][0] = -1e30f;
                if (col + 1 > lr0) s[nt][1] = -1e30f;
                if (col > lr0 + 8)     s[nt][2] = -1e30f;
                if (col + 1 > lr0 + 8) s[nt][3] = -1e30f;
            }
        }

        // ---- online softmax (rows lr0 and lr0+8)
        float rm0 = -1e30f, rm1 = -1e30f;
#pragma unroll
        for (int nt = 0; nt < 8; nt++) {
            rm0 = fmaxf(rm0, fmaxf(s[nt][0], s[nt][1]));
            rm1 = fmaxf(rm1, fmaxf(s[nt][2], s[nt][3]));
        }
        rm0 = fmaxf(rm0, __shfl_xor_sync(0xffffffffu, rm0, 1));
        rm0 = fmaxf(rm0, __shfl_xor_sync(0xffffffffu, rm0, 2));
        rm1 = fmaxf(rm1, __shfl_xor_sync(0xffffffffu, rm1, 1));
        rm1 = fmaxf(rm1, __shfl_xor_sync(0xffffffffu, rm1, 2));
        float mn0 = fmaxf(m0v, rm0), mn1 = fmaxf(m1v, rm1);
        float cor0 = __expf(m0v - mn0), cor1 = __expf(m1v - mn1);
        float sum0 = 0.0f, sum1 = 0.0f;
        uint32_t phi[4][4], plo[4][4];
#pragma unroll
        for (int nt = 0; nt < 8; nt++) {
            float p0 = __expf(s[nt][0] - mn0);
            float p1 = __expf(s[nt][1] - mn0);
            float p2 = __expf(s[nt][2] - mn1);
            float p3 = __expf(s[nt][3] - mn1);
            sum0 += p0 + p1; sum1 += p2 + p3;
            __nv_bfloat16 h0 = __float2bfloat16_rn(p0), h1 = __float2bfloat16_rn(p1);
            __nv_bfloat16 h2 = __float2bfloat16_rn(p2), h3 = __float2bfloat16_rn(p3);
            __nv_bfloat16 e0 = __float2bfloat16_rn(p0 - __bfloat162float(h0));
            __nv_bfloat16 e1 = __float2bfloat16_rn(p1 - __bfloat162float(h1));
            __nv_bfloat16 e2 = __float2bfloat16_rn(p2 - __bfloat162float(h2));
            __nv_bfloat16 e3 = __float2bfloat16_rn(p3 - __bfloat162float(h3));
            int ks = nt >> 1;                  // kstep (16 keys)
            int hi2 = nt & 1;                  // upper/lower 8 of k16
            __nv_bfloat162 ph01 = {h0, h1}, ph23 = {h2, h3};
            __nv_bfloat162 pl01 = {e0, e1}, pl23 = {e2, e3};
            phi[ks][hi2 * 2 + 0] = *(uint32_t*)&ph01;
            phi[ks][hi2 * 2 + 1] = *(uint32_t*)&ph23;
            plo[ks][hi2 * 2 + 0] = *(uint32_t*)&pl01;
            plo[ks][hi2 * 2 + 1] = *(uint32_t*)&pl23;
        }
        sum0 += __shfl_xor_sync(0xffffffffu, sum0, 1);
        sum0 += __shfl_xor_sync(0xffffffffu, sum0, 2);
        sum1 += __shfl_xor_sync(0xffffffffu, sum1, 1);
        sum1 += __shfl_xor_sync(0xffffffffu, sum1, 2);
        l0 = l0 * cor0 + sum0;
        l1 = l1 * cor1 + sum1;
        m0v = mn0; m1v = mn1;
#pragma unroll
        for (int nt = 0; nt < 16; nt++) {
            o[nt][0] *= cor0; o[nt][1] *= cor0;
            o[nt][2] *= cor1; o[nt][3] *= cor1;
        }

        // ---- O += P·V  3-pass
#pragma unroll
        for (int pass = 0; pass < 3; pass++) {
            const uint32_t vbase = (pass == 1) ? FVLO * 2 : FVHI * 2;
            uint32_t (*pf)[4] = (pass == 2) ? plo : phi;
#pragma unroll
            for (int ks = 0; ks < 4; ks++) {
#pragma unroll
                for (int nt2 = 0; nt2 < 8; nt2++) {
                    uint32_t voff = sb + vbase +
                        (uint32_t)((ks * 16 + (lane & 15)) * FPH + nt2 * 16 + (lane >> 4) * 8) * 2;
                    uint32_t b0, b1, b2, b3;
                    ldm_x4_t(b0, b1, b2, b3, voff);
                    mma_bf16(o[nt2 * 2 + 0], pf[ks], b0, b1);
                    mma_bf16(o[nt2 * 2 + 1], pf[ks], b2, b3);
                }
            }
        }
    }

    // ---- epilogue: y = O/l, write bf16 hi/lo to [B,T,C]
    const int b = bh / NHH, h = bh % NHH;
    const int r0 = wr + (lane >> 2);
    const int cbase = (lane & 3) * 2;
    float inv0 = 1.0f / l0, inv1 = 1.0f / l1;
    size_t rowA = (size_t)(b * TT + q0 + r0) * CC + h * HDD;
    size_t rowB = (size_t)(b * TT + q0 + r0 + 8) * CC + h * HDD;
#pragma unroll
    for (int nt = 0; nt < 16; nt++) {
        int col = nt * 8 + cbase;
        float y0 = o[nt][0] * inv0, y1 = o[nt][1] * inv0;
        float y2 = o[nt][2] * inv1, y3 = o[nt][3] * inv1;
        __nv_bfloat16 h0 = __float2bfloat16_rn(y0), h1 = __float2bfloat16_rn(y1);
        __nv_bfloat16 h2 = __float2bfloat16_rn(y2), h3 = __float2bfloat16_rn(y3);
        __nv_bfloat162 hi01 = {h0, h1}, hi23 = {h2, h3};
        __nv_bfloat162 lo01 = {__float2bfloat16_rn(y0 - __bfloat162float(h0)),
                               __float2bfloat16_rn(y1 - __bfloat162float(h1))};
        __nv_bfloat162 lo23 = {__float2bfloat16_rn(y2 - __bfloat162float(h2)),
                               __float2bfloat16_rn(y3 - __bfloat162float(h3))};
        *(uint32_t*)&Yhi[rowA + col] = *(uint32_t*)&hi01;
        *(uint32_t*)&Ylo[rowA + col] = *(uint32_t*)&lo01;
        *(uint32_t*)&Yhi[rowB + col] = *(uint32_t*)&hi23;
        *(uint32_t*)&Ylo[rowB + col] = *(uint32_t*)&lo23;
    }
}

// ===================== launch =====================
extern "C" void kernel_launch(void* const* d_in, const int* in_sizes, int n_in,
                              void* d_out, int out_size)
{
    const float* x           = (const float*)d_in[0];
    const int*   attn_w      = (const int*)d_in[1];
    const float* attn_scales = (const float*)d_in[2];
    const int*   proj_w      = (const int*)d_in[3];
    const float* proj_scales = (const float*)d_in[4];
    const float* qk_gain     = (const float*)d_in[5];
    float* out = (float*)d_out;

    float* p_qkv;
    __nv_bfloat16 *p_wa, *p_wp, *p_xhi, *p_xlo;
    __nv_bfloat16 *p_qhi, *p_qlo, *p_khi, *p_klo, *p_vhi, *p_vlo, *p_yhi, *p_ylo;
    cudaGetSymbolAddress((void**)&p_qkv, g_qkv);
    cudaGetSymbolAddress((void**)&p_wa,  g_wa);
    cudaGetSymbolAddress((void**)&p_wp,  g_wp);
    cudaGetSymbolAddress((void**)&p_xhi, g_xhi);
    cudaGetSymbolAddress((void**)&p_xlo, g_xlo);
    cudaGetSymbolAddress((void**)&p_qhi, g_qhi);
    cudaGetSymbolAddress((void**)&p_qlo, g_qlo);
    cudaGetSymbolAddress((void**)&p_khi, g_khi);
    cudaGetSymbolAddress((void**)&p_klo, g_klo);
    cudaGetSymbolAddress((void**)&p_vhi, g_vhi);
    cudaGetSymbolAddress((void**)&p_vlo, g_vlo);
    cudaGetSymbolAddress((void**)&p_yhi, g_yhi);
    cudaGetSymbolAddress((void**)&p_ylo, g_ylo);

    cudaFuncSetAttribute(gemm_mma_bf16, cudaFuncAttributeMaxDynamicSharedMemorySize, GEMM_SMEM);
    cudaFuncSetAttribute(flash_mma_kernel, cudaFuncAttributeMaxDynamicSharedMemorySize, FLASH_SMEM);

    // 0) weight conversions (int32 -> bf16, exact)
    conv_w_kernel<<<(THREEC * CC / 4 + 255) / 256, 256>>>(attn_w, p_wa, THREEC * CC / 4);
    conv_w_kernel<<<(CC * CC / 4 + 255) / 256, 256>>>(proj_w, p_wp, CC * CC / 4);

    // 1) x -> hi/lo bf16
    conv_split_kernel<<<(MTOK * CC / 4 + 255) / 256, 256>>>(x, p_xhi, p_xlo, MTOK * CC / 4);

    // 2) QKV = x @ Wa^T
    gemm_mma_bf16<<<dim3(THREEC / BN, MTOK / BM), 256, GEMM_SMEM>>>(
        p_xhi, p_xlo, p_wa, attn_scales, p_qkv, THREEC, CC);

    // 3) split + L2 norm -> bf16 hi/lo q/k/v
    split_norm_kernel<<<3 * BB * TT * NHH / 8, 256>>>(
        p_qkv, qk_gain, p_qhi, p_qlo, p_khi, p_klo, p_vhi, p_vlo);

    // 4) HMMA flash attention -> yhi/ylo
    flash_mma_kernel<<<dim3(TT / 64, BB * NHH), 128, FLASH_SMEM>>>(
        p_qhi, p_qlo, p_khi, p_klo, p_vhi, p_vlo, p_yhi, p_ylo);

    // 5) out = y @ Wp^T
    gemm_mma_bf16<<<dim3(CC / BN, MTOK / BM), 256, GEMM_SMEM>>>(
        p_yhi, p_ylo, p_wp, proj_scales, out, CC, CC);
}